// round 5
// baseline (speedup 1.0000x reference)
#include <cuda_runtime.h>
#include <cuda_fp16.h>
#include <cuda_bf16.h>
#include <math.h>

// Problem constants (fixed-shape problem)
#define NN 100000          // nodes
#define NE 3200000         // edges
#define F0 256             // in feats
#define F1 32              // hidden
#define F2 40              // out feats
#define CHUNK 1024
#define NB ((NN + CHUNK - 1) / CHUNK)   // 98 scan chunks
#define WT_STRIDE 260                   // 256 + 4 pad: conflict-free LDS.128
#define G1_GROUPS ((NN + 63) / 64)      // blocks, 64 rows/block

typedef unsigned long long ull;

// ---------------- scratch (static device globals; no runtime alloc) -------
__device__ int     g_deg_out[NN];
__device__ int     g_deg_in[NN];
__device__ float   g_inv_out[NN];
__device__ float   g_inv_in[NN];
__device__ int     g_rowptr[NN + 1];
__device__ int     g_cursor[NN];
__device__ int     g_chunksum[128];
__device__ int     g_chunkoff[128];
__device__ int     g_esrc[NE];
__device__ uint2   g_h1[NN * 8];   // fp16 rows, 8 x uint2 (=16 half2) per node
__device__ uint2   g_hs[NN * 8];

// ---------------- f32x2 packed helpers (sm_10x) ---------------------------
__device__ __forceinline__ ull pack2(float lo, float hi) {
    ull d;
    asm("mov.b64 %0, {%1, %2};" : "=l"(d)
        : "r"(__float_as_uint(lo)), "r"(__float_as_uint(hi)));
    return d;
}
__device__ __forceinline__ void fma2(ull& d, ull a, ull b) {
    asm("fma.rn.f32x2 %0, %1, %2, %0;" : "+l"(d) : "l"(a), "l"(b));
}
__device__ __forceinline__ float2 unpack2(ull v) {
    unsigned int lo, hi;
    asm("mov.b64 {%0, %1}, %2;" : "=r"(lo), "=r"(hi) : "l"(v));
    return make_float2(__uint_as_float(lo), __uint_as_float(hi));
}

// ---------------- CSR build kernels ---------------------------------------

__global__ void zero_kernel() {
    int i = blockIdx.x * blockDim.x + threadIdx.x;
    if (i < NN) { g_deg_out[i] = 0; g_deg_in[i] = 0; }
}

__global__ void degree_kernel(const int* __restrict__ src,
                              const int* __restrict__ dst) {
    int e = blockIdx.x * blockDim.x + threadIdx.x;
    if (e < NE) {
        atomicAdd(&g_deg_out[src[e]], 1);
        atomicAdd(&g_deg_in[dst[e]], 1);
    }
}

__global__ void scan1_kernel() {
    __shared__ int sm[CHUNK];
    int b = blockIdx.x, t = threadIdx.x;
    int i = b * CHUNK + t;
    int v = (i < NN) ? g_deg_in[i] : 0;
    if (i < NN) g_inv_in[i] = rsqrtf(fmaxf((float)v, 1.0f));
    sm[t] = v;
    __syncthreads();
    for (int o = 1; o < CHUNK; o <<= 1) {
        int add = (t >= o) ? sm[t - o] : 0;
        __syncthreads();
        sm[t] += add;
        __syncthreads();
    }
    if (i < NN) g_rowptr[i] = sm[t] - v;
    if (t == CHUNK - 1) g_chunksum[b] = sm[t];
}

__global__ void scan2_kernel() {
    __shared__ int sm[128];
    int t = threadIdx.x;
    int v = (t < NB) ? g_chunksum[t] : 0;
    sm[t] = v;
    __syncthreads();
    for (int o = 1; o < 128; o <<= 1) {
        int add = (t >= o) ? sm[t - o] : 0;
        __syncthreads();
        sm[t] += add;
        __syncthreads();
    }
    if (t < NB) g_chunkoff[t] = sm[t] - v;
}

__global__ void scan3_kernel() {
    int i = blockIdx.x * blockDim.x + threadIdx.x;
    if (i < NN) {
        int r = g_rowptr[i] + g_chunkoff[i / CHUNK];
        g_rowptr[i] = r;
        g_cursor[i] = r;
        g_inv_out[i] = rsqrtf(fmaxf((float)g_deg_out[i], 1.0f));
    }
    if (i == 0) g_rowptr[NN] = NE;
}

__global__ void bin_kernel(const int* __restrict__ src,
                           const int* __restrict__ dst) {
    int e = blockIdx.x * blockDim.x + threadIdx.x;
    if (e < NE) {
        int d = dst[e];
        int pos = atomicAdd(&g_cursor[d], 1);
        g_esrc[pos] = src[e];
    }
}

// ---------------- gemm1: h1 = (x * inv_out) @ W1 -> fp16 rows --------------
// 8 warps/block, 8 rows/warp (4 row-pairs). x staged pair-interleaved so the
// f32x2 b-operand comes directly from LDS.128 (no per-element packing).
__global__ void gemm1_kernel(const float* __restrict__ x,
                             const float* __restrict__ W1) {
    extern __shared__ float sm[];
    float* Wt = sm;                         // [32][WT_STRIDE] transposed W1
    float* xs = sm + F1 * WT_STRIDE;        // [8 warps][4 pairs][256][2]
    int tid = threadIdx.x;
    for (int i = tid; i < F0 * F1; i += blockDim.x) {
        int k = i >> 5, c = i & 31;
        Wt[c * WT_STRIDE + k] = W1[i];
    }
    __syncthreads();
    int warp = tid >> 5, lane = tid & 31;
    float* xp = xs + warp * (4 * 2 * F0);   // 2048 floats per warp
    int base = blockIdx.x * 64 + warp * 8;

    // stage 4 row-pairs, element-interleaved: xp[p][k] = {x[r0][k], x[r1][k]}
    #pragma unroll
    for (int p = 0; p < 4; p++) {
        int r0 = base + 2 * p, r1 = r0 + 1;
        if (r0 >= NN) r0 = NN - 1;
        if (r1 >= NN) r1 = NN - 1;
        const float4* x0 = (const float4*)(x + (size_t)r0 * F0);
        const float4* x1 = (const float4*)(x + (size_t)r1 * F0);
        float4* dstp = (float4*)(xp + p * 2 * F0);
        #pragma unroll
        for (int h = 0; h < 2; h++) {
            float4 a = x0[lane + 32 * h];
            float4 b = x1[lane + 32 * h];
            dstp[(lane + 32 * h) * 2 + 0] = make_float4(a.x, b.x, a.y, b.y);
            dstp[(lane + 32 * h) * 2 + 1] = make_float4(a.z, b.z, a.w, b.w);
        }
    }
    __syncwarp();

    ull acc0 = 0ull, acc1 = 0ull, acc2 = 0ull, acc3 = 0ull;
    const float* wrow = Wt + lane * WT_STRIDE;

    #pragma unroll 2
    for (int kq = 0; kq < F0 / 4; kq++) {
        float4 w4 = *(const float4*)(wrow + kq * 4);
        ull wd0 = pack2(w4.x, w4.x);
        ull wd1 = pack2(w4.y, w4.y);
        ull wd2 = pack2(w4.z, w4.z);
        ull wd3 = pack2(w4.w, w4.w);
        {
            ulonglong2 u = *(const ulonglong2*)(xp + 0 * 2 * F0 + kq * 8);
            ulonglong2 v = *(const ulonglong2*)(xp + 0 * 2 * F0 + kq * 8 + 4);
            fma2(acc0, wd0, u.x); fma2(acc0, wd1, u.y);
            fma2(acc0, wd2, v.x); fma2(acc0, wd3, v.y);
        }
        {
            ulonglong2 u = *(const ulonglong2*)(xp + 1 * 2 * F0 + kq * 8);
            ulonglong2 v = *(const ulonglong2*)(xp + 1 * 2 * F0 + kq * 8 + 4);
            fma2(acc1, wd0, u.x); fma2(acc1, wd1, u.y);
            fma2(acc1, wd2, v.x); fma2(acc1, wd3, v.y);
        }
        {
            ulonglong2 u = *(const ulonglong2*)(xp + 2 * 2 * F0 + kq * 8);
            ulonglong2 v = *(const ulonglong2*)(xp + 2 * 2 * F0 + kq * 8 + 4);
            fma2(acc2, wd0, u.x); fma2(acc2, wd1, u.y);
            fma2(acc2, wd2, v.x); fma2(acc2, wd3, v.y);
        }
        {
            ulonglong2 u = *(const ulonglong2*)(xp + 3 * 2 * F0 + kq * 8);
            ulonglong2 v = *(const ulonglong2*)(xp + 3 * 2 * F0 + kq * 8 + 4);
            fma2(acc3, wd0, u.x); fma2(acc3, wd1, u.y);
            fma2(acc3, wd2, v.x); fma2(acc3, wd3, v.y);
        }
    }

    __half* h1h = (__half*)g_h1;
    ull accs[4] = {acc0, acc1, acc2, acc3};
    #pragma unroll
    for (int p = 0; p < 4; p++) {
        float2 v = unpack2(accs[p]);
        int r0 = base + 2 * p, r1 = r0 + 1;
        if (r0 < NN) h1h[r0 * F1 + lane] = __float2half_rn(v.x * g_inv_out[r0]);
        if (r1 < NN) h1h[r1 * F1 + lane] = __float2half_rn(v.y * g_inv_out[r1]);
    }
}

// ---------------- aggregation: 8 lanes/row, 4 edges per gather instr -------
// lane = 8*slot + q; q covers features 4q..4q+3 via one uint2 (2x half2).

__device__ __forceinline__ void gather4(const uint2* __restrict__ tab,
                                        int idx, int q,
                                        float2& a0, float2& a1) {
    uint2 v = __ldg(&tab[idx * 8 + q]);
    float2 f0 = __half22float2(*(__half2*)&v.x);
    float2 f1 = __half22float2(*(__half2*)&v.y);
    a0.x += f0.x; a0.y += f0.y;
    a1.x += f1.x; a1.y += f1.y;
}

__global__ void agg1_kernel(const float* __restrict__ b1) {
    int gw = (blockIdx.x * blockDim.x + threadIdx.x) >> 5;
    int lane = threadIdx.x & 31;
    if (gw >= NN) return;
    int slot = lane >> 3, q = lane & 7;
    int s = g_rowptr[gw], e = g_rowptr[gw + 1];
    const uint2* tab = (const uint2*)g_h1;

    float2 a0 = make_float2(0.f, 0.f), a1 = make_float2(0.f, 0.f);
    float2 c0 = make_float2(0.f, 0.f), c1 = make_float2(0.f, 0.f);
    int j = s + slot;
    for (; j + 4 < e; j += 8) {
        int iA = __ldg(&g_esrc[j]);
        int iB = __ldg(&g_esrc[j + 4]);
        gather4(tab, iA, q, a0, a1);
        gather4(tab, iB, q, c0, c1);
    }
    if (j < e) gather4(tab, __ldg(&g_esrc[j]), q, a0, a1);
    a0.x += c0.x; a0.y += c0.y; a1.x += c1.x; a1.y += c1.y;

    #pragma unroll
    for (int o = 8; o <= 16; o <<= 1) {
        a0.x += __shfl_xor_sync(0xFFFFFFFFu, a0.x, o);
        a0.y += __shfl_xor_sync(0xFFFFFFFFu, a0.y, o);
        a1.x += __shfl_xor_sync(0xFFFFFFFFu, a1.x, o);
        a1.y += __shfl_xor_sync(0xFFFFFFFFu, a1.y, o);
    }

    if (lane < 8) {
        float inv_i = g_inv_in[gw], inv_o = g_inv_out[gw];
        float4 bb = __ldg((const float4*)b1 + q);
        float v0 = a0.x * inv_i + bb.x;
        float v1 = a0.y * inv_i + bb.y;
        float v2 = a1.x * inv_i + bb.z;
        float v3 = a1.y * inv_i + bb.w;
        v0 = (v0 > 0.f ? v0 : 0.f) * inv_o;
        v1 = (v1 > 0.f ? v1 : 0.f) * inv_o;
        v2 = (v2 > 0.f ? v2 : 0.f) * inv_o;
        v3 = (v3 > 0.f ? v3 : 0.f) * inv_o;
        uint2 outv;
        __half2 h0 = __floats2half2_rn(v0, v1);
        __half2 h1 = __floats2half2_rn(v2, v3);
        outv.x = *(unsigned int*)&h0;
        outv.y = *(unsigned int*)&h1;
        g_hs[gw * 8 + q] = outv;
    }
}

// agg2 fused: gather hs, *inv_in, @W2 + b2, log_softmax, write out.
__global__ void agg2_kernel(const float* __restrict__ W2,
                            const float* __restrict__ b2,
                            float* __restrict__ out) {
    __shared__ float W2s[F1 * F2];   // 5 KB
    __shared__ float sa[8][F1];
    for (int i = threadIdx.x; i < F1 * F2; i += blockDim.x) W2s[i] = W2[i];
    __syncthreads();

    int gw = (blockIdx.x * blockDim.x + threadIdx.x) >> 5;
    int warp = threadIdx.x >> 5, lane = threadIdx.x & 31;
    if (gw >= NN) return;
    int slot = lane >> 3, q = lane & 7;
    int s = g_rowptr[gw], e = g_rowptr[gw + 1];
    const uint2* tab = (const uint2*)g_hs;

    float2 a0 = make_float2(0.f, 0.f), a1 = make_float2(0.f, 0.f);
    float2 c0 = make_float2(0.f, 0.f), c1 = make_float2(0.f, 0.f);
    int j = s + slot;
    for (; j + 4 < e; j += 8) {
        int iA = __ldg(&g_esrc[j]);
        int iB = __ldg(&g_esrc[j + 4]);
        gather4(tab, iA, q, a0, a1);
        gather4(tab, iB, q, c0, c1);
    }
    if (j < e) gather4(tab, __ldg(&g_esrc[j]), q, a0, a1);
    a0.x += c0.x; a0.y += c0.y; a1.x += c1.x; a1.y += c1.y;

    #pragma unroll
    for (int o = 8; o <= 16; o <<= 1) {
        a0.x += __shfl_xor_sync(0xFFFFFFFFu, a0.x, o);
        a0.y += __shfl_xor_sync(0xFFFFFFFFu, a0.y, o);
        a1.x += __shfl_xor_sync(0xFFFFFFFFu, a1.x, o);
        a1.y += __shfl_xor_sync(0xFFFFFFFFu, a1.y, o);
    }

    float inv_i = g_inv_in[gw];
    if (lane < 8) {
        ((float4*)&sa[warp][0])[q] =
            make_float4(a0.x * inv_i, a0.y * inv_i, a1.x * inv_i, a1.y * inv_i);
    }
    __syncwarp();

    float v0 = b2[lane];
    float v1 = (lane < 8) ? b2[32 + lane] : -INFINITY;
    #pragma unroll
    for (int k = 0; k < F1; k++) {
        float ak = sa[warp][k];
        v0 = fmaf(ak, W2s[k * F2 + lane], v0);
        if (lane < 8) v1 = fmaf(ak, W2s[k * F2 + 32 + lane], v1);
    }

    float m = fmaxf(v0, v1);
    #pragma unroll
    for (int o = 16; o; o >>= 1) m = fmaxf(m, __shfl_xor_sync(0xFFFFFFFFu, m, o));
    float sum = expf(v0 - m) + ((lane < 8) ? expf(v1 - m) : 0.0f);
    #pragma unroll
    for (int o = 16; o; o >>= 1) sum += __shfl_xor_sync(0xFFFFFFFFu, sum, o);
    float L = m + logf(sum);
    out[gw * F2 + lane] = v0 - L;
    if (lane < 8) out[gw * F2 + 32 + lane] = v1 - L;
}

// ---------------- launcher ------------------------------------------------

extern "C" void kernel_launch(void* const* d_in, const int* in_sizes, int n_in,
                              void* d_out, int out_size) {
    const float* x   = (const float*)d_in[0];
    const float* W1  = (const float*)d_in[1];
    const float* b1  = (const float*)d_in[2];
    const float* W2  = (const float*)d_in[3];
    const float* b2  = (const float*)d_in[4];
    const int*   src = (const int*)d_in[5];
    const int*   dst = (const int*)d_in[6];
    float* out = (float*)d_out;

    const int TB = 256;
    int gN  = (NN + TB - 1) / TB;
    int gE  = (NE + TB - 1) / TB;
    int gWN = (NN * 32 + TB - 1) / TB;

    int g1_smem = (F1 * WT_STRIDE + 8 * 4 * 2 * F0) * (int)sizeof(float); // 98816 B
    cudaFuncSetAttribute(gemm1_kernel,
                         cudaFuncAttributeMaxDynamicSharedMemorySize, g1_smem);

    zero_kernel<<<gN, TB>>>();
    degree_kernel<<<gE, TB>>>(src, dst);
    scan1_kernel<<<NB, CHUNK>>>();
    scan2_kernel<<<1, 128>>>();
    scan3_kernel<<<gN, TB>>>();
    bin_kernel<<<gE, TB>>>(src, dst);

    gemm1_kernel<<<G1_GROUPS, TB, g1_smem>>>(x, W1);
    agg1_kernel<<<gWN, TB>>>(b1);
    agg2_kernel<<<gWN, TB>>>(W2, b2, out);
}

// round 7
// speedup vs baseline: 1.0175x; 1.0175x over previous
#include <cuda_runtime.h>
#include <cuda_fp16.h>
#include <cuda_bf16.h>
#include <math.h>

// Problem constants (fixed-shape problem)
#define NN 100000          // nodes
#define NE 3200000         // edges
#define F0 256             // in feats
#define F1 32              // hidden
#define F2 40              // out feats
#define CHUNK 1024
#define NB ((NN + CHUNK - 1) / CHUNK)   // 98 scan chunks
#define WT_STRIDE 260                   // 256 + 4 pad: conflict-free LDS.128
#define G1_GROUPS ((NN + 63) / 64)      // blocks, 64 rows/block

typedef unsigned long long ull;

// ---------------- scratch (static device globals; no runtime alloc) -------
__device__ int     g_deg_out[NN];
__device__ int     g_deg_in[NN];
__device__ float   g_inv_out[NN];
__device__ float   g_inv_in[NN];
__device__ int     g_rowptr[NN + 1];
__device__ int     g_cursor[NN];
__device__ int     g_chunksum[128];
__device__ int     g_chunkoff[128];
__device__ int     g_esrc[NE];
__device__ uint2   g_h1[NN * 8];   // fp16 rows, 8 x uint2 (=16 half2) per node
__device__ uint2   g_hs[NN * 8];

// ---------------- f32x2 packed helpers (sm_10x) ---------------------------
__device__ __forceinline__ ull pack2(float lo, float hi) {
    ull d;
    asm("mov.b64 %0, {%1, %2};" : "=l"(d)
        : "r"(__float_as_uint(lo)), "r"(__float_as_uint(hi)));
    return d;
}
__device__ __forceinline__ void fma2(ull& d, ull a, ull b) {
    asm("fma.rn.f32x2 %0, %1, %2, %0;" : "+l"(d) : "l"(a), "l"(b));
}
__device__ __forceinline__ float2 unpack2(ull v) {
    unsigned int lo, hi;
    asm("mov.b64 {%0, %1}, %2;" : "=r"(lo), "=r"(hi) : "l"(v));
    return make_float2(__uint_as_float(lo), __uint_as_float(hi));
}

// ---------------- CSR build kernels ---------------------------------------

__global__ void zero_kernel() {
    int i = blockIdx.x * blockDim.x + threadIdx.x;
    if (i < NN) { g_deg_out[i] = 0; g_deg_in[i] = 0; }
}

// 4 edges per thread via int4.
__global__ void degree_kernel(const int4* __restrict__ src4,
                              const int4* __restrict__ dst4) {
    int t = blockIdx.x * blockDim.x + threadIdx.x;
    if (t < NE / 4) {
        int4 s = __ldg(&src4[t]);
        int4 d = __ldg(&dst4[t]);
        atomicAdd(&g_deg_out[s.x], 1);
        atomicAdd(&g_deg_out[s.y], 1);
        atomicAdd(&g_deg_out[s.z], 1);
        atomicAdd(&g_deg_out[s.w], 1);
        atomicAdd(&g_deg_in[d.x], 1);
        atomicAdd(&g_deg_in[d.y], 1);
        atomicAdd(&g_deg_in[d.z], 1);
        atomicAdd(&g_deg_in[d.w], 1);
    }
}

__global__ void scan1_kernel() {
    __shared__ int sm[CHUNK];
    int b = blockIdx.x, t = threadIdx.x;
    int i = b * CHUNK + t;
    int v = (i < NN) ? g_deg_in[i] : 0;
    if (i < NN) g_inv_in[i] = rsqrtf(fmaxf((float)v, 1.0f));
    sm[t] = v;
    __syncthreads();
    for (int o = 1; o < CHUNK; o <<= 1) {
        int add = (t >= o) ? sm[t - o] : 0;
        __syncthreads();
        sm[t] += add;
        __syncthreads();
    }
    if (i < NN) g_rowptr[i] = sm[t] - v;
    if (t == CHUNK - 1) g_chunksum[b] = sm[t];
}

__global__ void scan2_kernel() {
    __shared__ int sm[128];
    int t = threadIdx.x;
    int v = (t < NB) ? g_chunksum[t] : 0;
    sm[t] = v;
    __syncthreads();
    for (int o = 1; o < 128; o <<= 1) {
        int add = (t >= o) ? sm[t - o] : 0;
        __syncthreads();
        sm[t] += add;
        __syncthreads();
    }
    if (t < NB) g_chunkoff[t] = sm[t] - v;
}

__global__ void scan3_kernel() {
    int i = blockIdx.x * blockDim.x + threadIdx.x;
    if (i < NN) {
        int r = g_rowptr[i] + g_chunkoff[i / CHUNK];
        g_rowptr[i] = r;
        g_cursor[i] = r;
        g_inv_out[i] = rsqrtf(fmaxf((float)g_deg_out[i], 1.0f));
    }
    if (i == 0) g_rowptr[NN] = NE;
}

// 4 edges per thread via int4.
__global__ void bin_kernel(const int4* __restrict__ src4,
                           const int4* __restrict__ dst4) {
    int t = blockIdx.x * blockDim.x + threadIdx.x;
    if (t < NE / 4) {
        int4 s = __ldg(&src4[t]);
        int4 d = __ldg(&dst4[t]);
        g_esrc[atomicAdd(&g_cursor[d.x], 1)] = s.x;
        g_esrc[atomicAdd(&g_cursor[d.y], 1)] = s.y;
        g_esrc[atomicAdd(&g_cursor[d.z], 1)] = s.z;
        g_esrc[atomicAdd(&g_cursor[d.w], 1)] = s.w;
    }
}

// ---------------- gemm1: h1 = x @ W1 (UNSCALED) -> fp16 rows ---------------
// Runs concurrently with the CSR build (no graph dependency).
__global__ void gemm1_kernel(const float* __restrict__ x,
                             const float* __restrict__ W1) {
    extern __shared__ float sm[];
    float* Wt = sm;                         // [32][WT_STRIDE] transposed W1
    float* xs = sm + F1 * WT_STRIDE;        // [8 warps][4 pairs][256][2]
    int tid = threadIdx.x;
    for (int i = tid; i < F0 * F1; i += blockDim.x) {
        int k = i >> 5, c = i & 31;
        Wt[c * WT_STRIDE + k] = W1[i];
    }
    __syncthreads();
    int warp = tid >> 5, lane = tid & 31;
    float* xp = xs + warp * (4 * 2 * F0);
    int base = blockIdx.x * 64 + warp * 8;

    #pragma unroll
    for (int p = 0; p < 4; p++) {
        int r0 = base + 2 * p, r1 = r0 + 1;
        if (r0 >= NN) r0 = NN - 1;
        if (r1 >= NN) r1 = NN - 1;
        const float4* x0 = (const float4*)(x + (size_t)r0 * F0);
        const float4* x1 = (const float4*)(x + (size_t)r1 * F0);
        float4* dstp = (float4*)(xp + p * 2 * F0);
        #pragma unroll
        for (int h = 0; h < 2; h++) {
            float4 a = x0[lane + 32 * h];
            float4 b = x1[lane + 32 * h];
            dstp[(lane + 32 * h) * 2 + 0] = make_float4(a.x, b.x, a.y, b.y);
            dstp[(lane + 32 * h) * 2 + 1] = make_float4(a.z, b.z, a.w, b.w);
        }
    }
    __syncwarp();

    ull acc0 = 0ull, acc1 = 0ull, acc2 = 0ull, acc3 = 0ull;
    const float* wrow = Wt + lane * WT_STRIDE;

    #pragma unroll 2
    for (int kq = 0; kq < F0 / 4; kq++) {
        float4 w4 = *(const float4*)(wrow + kq * 4);
        ull wd0 = pack2(w4.x, w4.x);
        ull wd1 = pack2(w4.y, w4.y);
        ull wd2 = pack2(w4.z, w4.z);
        ull wd3 = pack2(w4.w, w4.w);
        {
            ulonglong2 u = *(const ulonglong2*)(xp + 0 * 2 * F0 + kq * 8);
            ulonglong2 v = *(const ulonglong2*)(xp + 0 * 2 * F0 + kq * 8 + 4);
            fma2(acc0, wd0, u.x); fma2(acc0, wd1, u.y);
            fma2(acc0, wd2, v.x); fma2(acc0, wd3, v.y);
        }
        {
            ulonglong2 u = *(const ulonglong2*)(xp + 1 * 2 * F0 + kq * 8);
            ulonglong2 v = *(const ulonglong2*)(xp + 1 * 2 * F0 + kq * 8 + 4);
            fma2(acc1, wd0, u.x); fma2(acc1, wd1, u.y);
            fma2(acc1, wd2, v.x); fma2(acc1, wd3, v.y);
        }
        {
            ulonglong2 u = *(const ulonglong2*)(xp + 2 * 2 * F0 + kq * 8);
            ulonglong2 v = *(const ulonglong2*)(xp + 2 * 2 * F0 + kq * 8 + 4);
            fma2(acc2, wd0, u.x); fma2(acc2, wd1, u.y);
            fma2(acc2, wd2, v.x); fma2(acc2, wd3, v.y);
        }
        {
            ulonglong2 u = *(const ulonglong2*)(xp + 3 * 2 * F0 + kq * 8);
            ulonglong2 v = *(const ulonglong2*)(xp + 3 * 2 * F0 + kq * 8 + 4);
            fma2(acc3, wd0, u.x); fma2(acc3, wd1, u.y);
            fma2(acc3, wd2, v.x); fma2(acc3, wd3, v.y);
        }
    }

    __half* h1h = (__half*)g_h1;
    ull accs[4] = {acc0, acc1, acc2, acc3};
    #pragma unroll
    for (int p = 0; p < 4; p++) {
        float2 v = unpack2(accs[p]);
        int r0 = base + 2 * p, r1 = r0 + 1;
        if (r0 < NN) h1h[r0 * F1 + lane] = __float2half_rn(v.x);
        if (r1 < NN) h1h[r1 * F1 + lane] = __float2half_rn(v.y);
    }
}

// Scale h1 rows by inv_out (after join). 8 threads per node.
__global__ void scale_h1_kernel() {
    int i = blockIdx.x * blockDim.x + threadIdx.x;
    if (i >= NN * 8) return;
    float inv = g_inv_out[i >> 3];
    uint2 v = g_h1[i];
    float2 f0 = __half22float2(*(__half2*)&v.x);
    float2 f1 = __half22float2(*(__half2*)&v.y);
    __half2 h0 = __floats2half2_rn(f0.x * inv, f0.y * inv);
    __half2 h1 = __floats2half2_rn(f1.x * inv, f1.y * inv);
    v.x = *(unsigned int*)&h0;
    v.y = *(unsigned int*)&h1;
    g_h1[i] = v;
}

// ---------------- aggregation: 8 lanes/row, MLP-4 gathers ------------------
__device__ __forceinline__ void gather4(const uint2* __restrict__ tab,
                                        int idx, int q,
                                        float2& a0, float2& a1) {
    uint2 v = __ldg(&tab[idx * 8 + q]);
    float2 f0 = __half22float2(*(__half2*)&v.x);
    float2 f1 = __half22float2(*(__half2*)&v.y);
    a0.x += f0.x; a0.y += f0.y;
    a1.x += f1.x; a1.y += f1.y;
}

// Aggregates 16 half-feats (as 2x float2) for node gw across its in-edges.
__device__ __forceinline__ void agg_gather(const uint2* __restrict__ tab,
                                           int s, int e, int slot, int q,
                                           float2& r0, float2& r1) {
    float2 a0 = make_float2(0.f, 0.f), a1 = make_float2(0.f, 0.f);
    float2 b0 = make_float2(0.f, 0.f), b1 = make_float2(0.f, 0.f);
    float2 c0 = make_float2(0.f, 0.f), c1 = make_float2(0.f, 0.f);
    float2 d0 = make_float2(0.f, 0.f), d1 = make_float2(0.f, 0.f);
    int j = s + slot;
    for (; j + 12 < e; j += 16) {
        int i0 = __ldg(&g_esrc[j]);
        int i1 = __ldg(&g_esrc[j + 4]);
        int i2 = __ldg(&g_esrc[j + 8]);
        int i3 = __ldg(&g_esrc[j + 12]);
        gather4(tab, i0, q, a0, a1);
        gather4(tab, i1, q, b0, b1);
        gather4(tab, i2, q, c0, c1);
        gather4(tab, i3, q, d0, d1);
    }
    for (; j < e; j += 4) gather4(tab, __ldg(&g_esrc[j]), q, a0, a1);
    r0.x = (a0.x + b0.x) + (c0.x + d0.x);
    r0.y = (a0.y + b0.y) + (c0.y + d0.y);
    r1.x = (a1.x + b1.x) + (c1.x + d1.x);
    r1.y = (a1.y + b1.y) + (c1.y + d1.y);
    #pragma unroll
    for (int o = 8; o <= 16; o <<= 1) {
        r0.x += __shfl_xor_sync(0xFFFFFFFFu, r0.x, o);
        r0.y += __shfl_xor_sync(0xFFFFFFFFu, r0.y, o);
        r1.x += __shfl_xor_sync(0xFFFFFFFFu, r1.x, o);
        r1.y += __shfl_xor_sync(0xFFFFFFFFu, r1.y, o);
    }
}

__global__ void agg1_kernel(const float* __restrict__ b1) {
    int gw = (blockIdx.x * blockDim.x + threadIdx.x) >> 5;
    int lane = threadIdx.x & 31;
    if (gw >= NN) return;
    int slot = lane >> 3, q = lane & 7;
    int s = g_rowptr[gw], e = g_rowptr[gw + 1];
    float2 r0, r1;
    agg_gather((const uint2*)g_h1, s, e, slot, q, r0, r1);

    if (lane < 8) {
        float inv_i = g_inv_in[gw], inv_o = g_inv_out[gw];
        float4 bb = __ldg((const float4*)b1 + q);
        float v0 = r0.x * inv_i + bb.x;
        float v1 = r0.y * inv_i + bb.y;
        float v2 = r1.x * inv_i + bb.z;
        float v3 = r1.y * inv_i + bb.w;
        v0 = (v0 > 0.f ? v0 : 0.f) * inv_o;
        v1 = (v1 > 0.f ? v1 : 0.f) * inv_o;
        v2 = (v2 > 0.f ? v2 : 0.f) * inv_o;
        v3 = (v3 > 0.f ? v3 : 0.f) * inv_o;
        uint2 outv;
        __half2 h0 = __floats2half2_rn(v0, v1);
        __half2 h1 = __floats2half2_rn(v2, v3);
        outv.x = *(unsigned int*)&h0;
        outv.y = *(unsigned int*)&h1;
        g_hs[gw * 8 + q] = outv;
    }
}

__global__ void agg2_kernel(const float* __restrict__ W2,
                            const float* __restrict__ b2,
                            float* __restrict__ out) {
    __shared__ float W2s[F1 * F2];
    __shared__ float sa[8][F1];
    for (int i = threadIdx.x; i < F1 * F2; i += blockDim.x) W2s[i] = W2[i];
    __syncthreads();

    int gw = (blockIdx.x * blockDim.x + threadIdx.x) >> 5;
    int warp = threadIdx.x >> 5, lane = threadIdx.x & 31;
    if (gw >= NN) return;
    int slot = lane >> 3, q = lane & 7;
    int s = g_rowptr[gw], e = g_rowptr[gw + 1];
    float2 r0, r1;
    agg_gather((const uint2*)g_hs, s, e, slot, q, r0, r1);

    float inv_i = g_inv_in[gw];
    if (lane < 8) {
        ((float4*)&sa[warp][0])[q] =
            make_float4(r0.x * inv_i, r0.y * inv_i, r1.x * inv_i, r1.y * inv_i);
    }
    __syncwarp();

    float v0 = b2[lane];
    float v1 = (lane < 8) ? b2[32 + lane] : -INFINITY;
    #pragma unroll
    for (int k = 0; k < F1; k++) {
        float ak = sa[warp][k];
        v0 = fmaf(ak, W2s[k * F2 + lane], v0);
        if (lane < 8) v1 = fmaf(ak, W2s[k * F2 + 32 + lane], v1);
    }

    float m = fmaxf(v0, v1);
    #pragma unroll
    for (int o = 16; o; o >>= 1) m = fmaxf(m, __shfl_xor_sync(0xFFFFFFFFu, m, o));
    float sum = expf(v0 - m) + ((lane < 8) ? expf(v1 - m) : 0.0f);
    #pragma unroll
    for (int o = 16; o; o >>= 1) sum += __shfl_xor_sync(0xFFFFFFFFu, sum, o);
    float L = m + logf(sum);
    out[gw * F2 + lane] = v0 - L;
    if (lane < 8) out[gw * F2 + 32 + lane] = v1 - L;
}

// ---------------- launcher ------------------------------------------------

static cudaStream_t g_s2 = nullptr;
static cudaEvent_t  g_e0 = nullptr, g_e1 = nullptr;

extern "C" void kernel_launch(void* const* d_in, const int* in_sizes, int n_in,
                              void* d_out, int out_size) {
    const float* x   = (const float*)d_in[0];
    const float* W1  = (const float*)d_in[1];
    const float* b1  = (const float*)d_in[2];
    const float* W2  = (const float*)d_in[3];
    const float* b2  = (const float*)d_in[4];
    const int*   src = (const int*)d_in[5];
    const int*   dst = (const int*)d_in[6];
    float* out = (float*)d_out;

    if (g_s2 == nullptr) {
        cudaStreamCreateWithFlags(&g_s2, cudaStreamNonBlocking);
        cudaEventCreateWithFlags(&g_e0, cudaEventDisableTiming);
        cudaEventCreateWithFlags(&g_e1, cudaEventDisableTiming);
    }

    const int TB = 256;
    int gN   = (NN + TB - 1) / TB;
    int gE4  = (NE / 4 + TB - 1) / TB;
    int gWN  = (NN * 32 + TB - 1) / TB;
    int gSH  = (NN * 8 + TB - 1) / TB;

    int g1_smem = (F1 * WT_STRIDE + 8 * 4 * 2 * F0) * (int)sizeof(float); // 98816 B
    cudaFuncSetAttribute(gemm1_kernel,
                         cudaFuncAttributeMaxDynamicSharedMemorySize, g1_smem);

    // Fork: gemm1 (independent of graph) on side stream.
    cudaEventRecord(g_e0, 0);
    cudaStreamWaitEvent(g_s2, g_e0, 0);
    gemm1_kernel<<<G1_GROUPS, TB, g1_smem, g_s2>>>(x, W1);
    cudaEventRecord(g_e1, g_s2);

    // CSR build chain on main stream (concurrent with gemm1).
    zero_kernel<<<gN, TB>>>();
    degree_kernel<<<gE4, TB>>>((const int4*)src, (const int4*)dst);
    scan1_kernel<<<NB, CHUNK>>>();
    scan2_kernel<<<1, 128>>>();
    scan3_kernel<<<gN, TB>>>();
    bin_kernel<<<gE4, TB>>>((const int4*)src, (const int4*)dst);

    // Join: need gemm1 output + inv_out.
    cudaStreamWaitEvent(0, g_e1, 0);
    scale_h1_kernel<<<gSH, TB>>>();
    agg1_kernel<<<gWN, TB>>>(b1);
    agg2_kernel<<<gWN, TB>>>(W2, b2, out);
}

// round 9
// speedup vs baseline: 1.0427x; 1.0248x over previous
#include <cuda_runtime.h>
#include <cuda_fp16.h>
#include <cuda_bf16.h>
#include <math.h>

// Problem constants (fixed-shape problem)
#define NN 100000          // nodes
#define NE 3200000         // edges
#define F0 256             // in feats
#define F1 32              // hidden
#define F2 40              // out feats
#define CHUNK 1024
#define NB ((NN + CHUNK - 1) / CHUNK)   // 98 scan chunks
#define WT_STRIDE 260                   // 256 + 4 pad: conflict-free LDS.128
#define G1_GROUPS ((NN + 63) / 64)      // blocks, 64 rows/block

typedef unsigned long long ull;

// ---------------- scratch (static device globals; no runtime alloc) -------
__device__ int     g_deg_out[NN];
__device__ int     g_deg_in[NN];
__device__ float   g_inv_out[NN];
__device__ float   g_inv_in[NN];
__device__ int     g_start[NN];
__device__ int     g_cursor[NN];
__device__ int     g_total;
__device__ int     g_esrc[NE];
__device__ uint2   g_h1[NN * 8];   // fp16 rows, 8 x uint2 (=16 half2) per node
__device__ uint2   g_hs[NN * 8];

// ---------------- f32x2 packed helpers (sm_10x) ---------------------------
__device__ __forceinline__ ull pack2(float lo, float hi) {
    ull d;
    asm("mov.b64 %0, {%1, %2};" : "=l"(d)
        : "r"(__float_as_uint(lo)), "r"(__float_as_uint(hi)));
    return d;
}
__device__ __forceinline__ void fma2(ull& d, ull a, ull b) {
    asm("fma.rn.f32x2 %0, %1, %2, %0;" : "+l"(d) : "l"(a), "l"(b));
}
__device__ __forceinline__ float2 unpack2(ull v) {
    unsigned int lo, hi;
    asm("mov.b64 {%0, %1}, %2;" : "=r"(lo), "=r"(hi) : "l"(v));
    return make_float2(__uint_as_float(lo), __uint_as_float(hi));
}

// ---------------- CSR build kernels ---------------------------------------

// src histogram (side stream; feeds gemm1's inv_out).
__global__ void deg_out_kernel(const int4* __restrict__ src4) {
    int t = blockIdx.x * blockDim.x + threadIdx.x;
    if (t < NE / 4) {
        int4 s = __ldg(&src4[t]);
        atomicAdd(&g_deg_out[s.x], 1);
        atomicAdd(&g_deg_out[s.y], 1);
        atomicAdd(&g_deg_out[s.z], 1);
        atomicAdd(&g_deg_out[s.w], 1);
    }
}

// dst histogram (main stream).
__global__ void deg_in_kernel(const int4* __restrict__ dst4) {
    int t = blockIdx.x * blockDim.x + threadIdx.x;
    if (t < NE / 4) {
        int4 d = __ldg(&dst4[t]);
        atomicAdd(&g_deg_in[d.x], 1);
        atomicAdd(&g_deg_in[d.y], 1);
        atomicAdd(&g_deg_in[d.z], 1);
        atomicAdd(&g_deg_in[d.w], 1);
    }
}

// Single-pass "scan": per-chunk exclusive scan + atomic chunk base.
// g_start is NOT globally monotone; each node owns [start, start+deg).
__global__ void scan_fused_kernel() {
    __shared__ int sm[CHUNK];
    __shared__ int sbase;
    int b = blockIdx.x, t = threadIdx.x;
    int i = b * CHUNK + t;
    int v = (i < NN) ? g_deg_in[i] : 0;
    if (i < NN) g_inv_in[i] = rsqrtf(fmaxf((float)v, 1.0f));
    sm[t] = v;
    __syncthreads();
    for (int o = 1; o < CHUNK; o <<= 1) {
        int add = (t >= o) ? sm[t - o] : 0;
        __syncthreads();
        sm[t] += add;
        __syncthreads();
    }
    if (t == CHUNK - 1) sbase = atomicAdd(&g_total, sm[t]);
    __syncthreads();
    if (i < NN) {
        int st = sbase + sm[t] - v;
        g_start[i] = st;
        g_cursor[i] = st;
    }
}

// Bin edges by dst into g_esrc; 4 edges per thread.
__global__ void bin_kernel(const int4* __restrict__ src4,
                           const int4* __restrict__ dst4) {
    int t = blockIdx.x * blockDim.x + threadIdx.x;
    if (t < NE / 4) {
        int4 s = __ldg(&src4[t]);
        int4 d = __ldg(&dst4[t]);
        g_esrc[atomicAdd(&g_cursor[d.x], 1)] = s.x;
        g_esrc[atomicAdd(&g_cursor[d.y], 1)] = s.y;
        g_esrc[atomicAdd(&g_cursor[d.z], 1)] = s.z;
        g_esrc[atomicAdd(&g_cursor[d.w], 1)] = s.w;
    }
}

// ---------------- gemm1: h1 = (x * inv_out) @ W1 -> fp16 rows --------------
// Computes inv_out inline from deg_out (side stream: after deg_out_kernel).
__global__ void gemm1_kernel(const float* __restrict__ x,
                             const float* __restrict__ W1) {
    extern __shared__ float sm[];
    float* Wt = sm;                         // [32][WT_STRIDE] transposed W1
    float* xs = sm + F1 * WT_STRIDE;        // [8 warps][4 pairs][256][2]
    int tid = threadIdx.x;
    for (int i = tid; i < F0 * F1; i += blockDim.x) {
        int k = i >> 5, c = i & 31;
        Wt[c * WT_STRIDE + k] = W1[i];
    }
    __syncthreads();
    int warp = tid >> 5, lane = tid & 31;
    float* xp = xs + warp * (4 * 2 * F0);
    int base = blockIdx.x * 64 + warp * 8;

    // inv_out for this warp's 8 rows (lane&7 indexes the row).
    int rl = base + (lane & 7);
    if (rl >= NN) rl = NN - 1;
    float iv = rsqrtf(fmaxf((float)g_deg_out[rl], 1.0f));
    if (lane < 8 && base + lane < NN) g_inv_out[base + lane] = iv;

    #pragma unroll
    for (int p = 0; p < 4; p++) {
        int r0 = base + 2 * p, r1 = r0 + 1;
        if (r0 >= NN) r0 = NN - 1;
        if (r1 >= NN) r1 = NN - 1;
        const float4* x0 = (const float4*)(x + (size_t)r0 * F0);
        const float4* x1 = (const float4*)(x + (size_t)r1 * F0);
        float4* dstp = (float4*)(xp + p * 2 * F0);
        #pragma unroll
        for (int h = 0; h < 2; h++) {
            float4 a = x0[lane + 32 * h];
            float4 b = x1[lane + 32 * h];
            dstp[(lane + 32 * h) * 2 + 0] = make_float4(a.x, b.x, a.y, b.y);
            dstp[(lane + 32 * h) * 2 + 1] = make_float4(a.z, b.z, a.w, b.w);
        }
    }
    __syncwarp();

    ull acc0 = 0ull, acc1 = 0ull, acc2 = 0ull, acc3 = 0ull;
    const float* wrow = Wt + lane * WT_STRIDE;

    #pragma unroll 2
    for (int kq = 0; kq < F0 / 4; kq++) {
        float4 w4 = *(const float4*)(wrow + kq * 4);
        ull wd0 = pack2(w4.x, w4.x);
        ull wd1 = pack2(w4.y, w4.y);
        ull wd2 = pack2(w4.z, w4.z);
        ull wd3 = pack2(w4.w, w4.w);
        {
            ulonglong2 u = *(const ulonglong2*)(xp + 0 * 2 * F0 + kq * 8);
            ulonglong2 v = *(const ulonglong2*)(xp + 0 * 2 * F0 + kq * 8 + 4);
            fma2(acc0, wd0, u.x); fma2(acc0, wd1, u.y);
            fma2(acc0, wd2, v.x); fma2(acc0, wd3, v.y);
        }
        {
            ulonglong2 u = *(const ulonglong2*)(xp + 1 * 2 * F0 + kq * 8);
            ulonglong2 v = *(const ulonglong2*)(xp + 1 * 2 * F0 + kq * 8 + 4);
            fma2(acc1, wd0, u.x); fma2(acc1, wd1, u.y);
            fma2(acc1, wd2, v.x); fma2(acc1, wd3, v.y);
        }
        {
            ulonglong2 u = *(const ulonglong2*)(xp + 2 * 2 * F0 + kq * 8);
            ulonglong2 v = *(const ulonglong2*)(xp + 2 * 2 * F0 + kq * 8 + 4);
            fma2(acc2, wd0, u.x); fma2(acc2, wd1, u.y);
            fma2(acc2, wd2, v.x); fma2(acc2, wd3, v.y);
        }
        {
            ulonglong2 u = *(const ulonglong2*)(xp + 3 * 2 * F0 + kq * 8);
            ulonglong2 v = *(const ulonglong2*)(xp + 3 * 2 * F0 + kq * 8 + 4);
            fma2(acc3, wd0, u.x); fma2(acc3, wd1, u.y);
            fma2(acc3, wd2, v.x); fma2(acc3, wd3, v.y);
        }
    }

    __half* h1h = (__half*)g_h1;
    ull accs[4] = {acc0, acc1, acc2, acc3};
    #pragma unroll
    for (int p = 0; p < 4; p++) {
        float2 v = unpack2(accs[p]);
        float iv0 = __shfl_sync(0xFFFFFFFFu, iv, 2 * p);
        float iv1 = __shfl_sync(0xFFFFFFFFu, iv, 2 * p + 1);
        int r0 = base + 2 * p, r1 = r0 + 1;
        if (r0 < NN) h1h[r0 * F1 + lane] = __float2half_rn(v.x * iv0);
        if (r1 < NN) h1h[r1 * F1 + lane] = __float2half_rn(v.y * iv1);
    }
}

// ---------------- aggregation: 8 lanes/row, MLP-4 gathers ------------------
__device__ __forceinline__ void gather4(const uint2* __restrict__ tab,
                                        int idx, int q,
                                        float2& a0, float2& a1) {
    uint2 v = __ldg(&tab[idx * 8 + q]);
    float2 f0 = __half22float2(*(__half2*)&v.x);
    float2 f1 = __half22float2(*(__half2*)&v.y);
    a0.x += f0.x; a0.y += f0.y;
    a1.x += f1.x; a1.y += f1.y;
}

__device__ __forceinline__ void agg_gather(const uint2* __restrict__ tab,
                                           int s, int e, int slot, int q,
                                           float2& r0, float2& r1) {
    float2 a0 = make_float2(0.f, 0.f), a1 = make_float2(0.f, 0.f);
    float2 b0 = make_float2(0.f, 0.f), b1 = make_float2(0.f, 0.f);
    float2 c0 = make_float2(0.f, 0.f), c1 = make_float2(0.f, 0.f);
    float2 d0 = make_float2(0.f, 0.f), d1 = make_float2(0.f, 0.f);
    int j = s + slot;
    for (; j + 12 < e; j += 16) {
        int i0 = __ldg(&g_esrc[j]);
        int i1 = __ldg(&g_esrc[j + 4]);
        int i2 = __ldg(&g_esrc[j + 8]);
        int i3 = __ldg(&g_esrc[j + 12]);
        gather4(tab, i0, q, a0, a1);
        gather4(tab, i1, q, b0, b1);
        gather4(tab, i2, q, c0, c1);
        gather4(tab, i3, q, d0, d1);
    }
    for (; j < e; j += 4) gather4(tab, __ldg(&g_esrc[j]), q, a0, a1);
    r0.x = (a0.x + b0.x) + (c0.x + d0.x);
    r0.y = (a0.y + b0.y) + (c0.y + d0.y);
    r1.x = (a1.x + b1.x) + (c1.x + d1.x);
    r1.y = (a1.y + b1.y) + (c1.y + d1.y);
    #pragma unroll
    for (int o = 8; o <= 16; o <<= 1) {
        r0.x += __shfl_xor_sync(0xFFFFFFFFu, r0.x, o);
        r0.y += __shfl_xor_sync(0xFFFFFFFFu, r0.y, o);
        r1.x += __shfl_xor_sync(0xFFFFFFFFu, r1.x, o);
        r1.y += __shfl_xor_sync(0xFFFFFFFFu, r1.y, o);
    }
}

__global__ void agg1_kernel(const float* __restrict__ b1) {
    int gw = (blockIdx.x * blockDim.x + threadIdx.x) >> 5;
    int lane = threadIdx.x & 31;
    if (gw >= NN) return;
    int slot = lane >> 3, q = lane & 7;
    int s = g_start[gw], e = s + g_deg_in[gw];
    float2 r0, r1;
    agg_gather((const uint2*)g_h1, s, e, slot, q, r0, r1);

    if (lane < 8) {
        float inv_i = g_inv_in[gw], inv_o = g_inv_out[gw];
        float4 bb = __ldg((const float4*)b1 + q);
        float v0 = r0.x * inv_i + bb.x;
        float v1 = r0.y * inv_i + bb.y;
        float v2 = r1.x * inv_i + bb.z;
        float v3 = r1.y * inv_i + bb.w;
        v0 = (v0 > 0.f ? v0 : 0.f) * inv_o;
        v1 = (v1 > 0.f ? v1 : 0.f) * inv_o;
        v2 = (v2 > 0.f ? v2 : 0.f) * inv_o;
        v3 = (v3 > 0.f ? v3 : 0.f) * inv_o;
        uint2 outv;
        __half2 h0 = __floats2half2_rn(v0, v1);
        __half2 h1 = __floats2half2_rn(v2, v3);
        outv.x = *(unsigned int*)&h0;
        outv.y = *(unsigned int*)&h1;
        g_hs[gw * 8 + q] = outv;
    }
}

__global__ void agg2_kernel(const float* __restrict__ W2,
                            const float* __restrict__ b2,
                            float* __restrict__ out) {
    __shared__ float W2s[F1 * F2];
    __shared__ float sa[8][F1];
    for (int i = threadIdx.x; i < F1 * F2; i += blockDim.x) W2s[i] = W2[i];
    __syncthreads();

    int gw = (blockIdx.x * blockDim.x + threadIdx.x) >> 5;
    int warp = threadIdx.x >> 5, lane = threadIdx.x & 31;
    if (gw >= NN) return;
    int slot = lane >> 3, q = lane & 7;
    int s = g_start[gw], e = s + g_deg_in[gw];
    float2 r0, r1;
    agg_gather((const uint2*)g_hs, s, e, slot, q, r0, r1);

    float inv_i = g_inv_in[gw];
    if (lane < 8) {
        ((float4*)&sa[warp][0])[q] =
            make_float4(r0.x * inv_i, r0.y * inv_i, r1.x * inv_i, r1.y * inv_i);
    }
    __syncwarp();

    float v0 = b2[lane];
    float v1 = (lane < 8) ? b2[32 + lane] : -INFINITY;
    #pragma unroll
    for (int k = 0; k < F1; k++) {
        float ak = sa[warp][k];
        v0 = fmaf(ak, W2s[k * F2 + lane], v0);
        if (lane < 8) v1 = fmaf(ak, W2s[k * F2 + 32 + lane], v1);
    }

    float m = fmaxf(v0, v1);
    #pragma unroll
    for (int o = 16; o; o >>= 1) m = fmaxf(m, __shfl_xor_sync(0xFFFFFFFFu, m, o));
    float sum = expf(v0 - m) + ((lane < 8) ? expf(v1 - m) : 0.0f);
    #pragma unroll
    for (int o = 16; o; o >>= 1) sum += __shfl_xor_sync(0xFFFFFFFFu, sum, o);
    float L = m + logf(sum);
    out[gw * F2 + lane] = v0 - L;
    if (lane < 8) out[gw * F2 + 32 + lane] = v1 - L;
}

// ---------------- launcher ------------------------------------------------

static cudaStream_t g_s2 = nullptr;
static cudaEvent_t  g_e0 = nullptr, g_e1 = nullptr;
static void* p_degout = nullptr;
static void* p_degin  = nullptr;
static void* p_total  = nullptr;

extern "C" void kernel_launch(void* const* d_in, const int* in_sizes, int n_in,
                              void* d_out, int out_size) {
    const float* x   = (const float*)d_in[0];
    const float* W1  = (const float*)d_in[1];
    const float* b1  = (const float*)d_in[2];
    const float* W2  = (const float*)d_in[3];
    const float* b2  = (const float*)d_in[4];
    const int*   src = (const int*)d_in[5];
    const int*   dst = (const int*)d_in[6];
    float* out = (float*)d_out;

    if (g_s2 == nullptr) {
        cudaStreamCreateWithFlags(&g_s2, cudaStreamNonBlocking);
        cudaEventCreateWithFlags(&g_e0, cudaEventDisableTiming);
        cudaEventCreateWithFlags(&g_e1, cudaEventDisableTiming);
        cudaGetSymbolAddress(&p_degout, g_deg_out);
        cudaGetSymbolAddress(&p_degin,  g_deg_in);
        cudaGetSymbolAddress(&p_total,  g_total);
    }

    const int TB = 256;
    int gE4  = (NE / 4 + TB - 1) / TB;
    int gWN  = (NN * 32 + TB - 1) / TB;

    int g1_smem = (F1 * WT_STRIDE + 8 * 4 * 2 * F0) * (int)sizeof(float); // 98816 B
    cudaFuncSetAttribute(gemm1_kernel,
                         cudaFuncAttributeMaxDynamicSharedMemorySize, g1_smem);

    // Fork.
    cudaEventRecord(g_e0, 0);
    cudaStreamWaitEvent(g_s2, g_e0, 0);

    // Side stream: deg_out histogram -> gemm1 (inv_out fused, h1 pre-scaled).
    cudaMemsetAsync(p_degout, 0, NN * sizeof(int), g_s2);
    deg_out_kernel<<<gE4, TB, 0, g_s2>>>((const int4*)src);
    gemm1_kernel<<<G1_GROUPS, TB, g1_smem, g_s2>>>(x, W1);
    cudaEventRecord(g_e1, g_s2);

    // Main stream: deg_in -> fused scan -> bin.
    cudaMemsetAsync(p_degin, 0, NN * sizeof(int), 0);
    cudaMemsetAsync(p_total, 0, sizeof(int), 0);
    deg_in_kernel<<<gE4, TB>>>((const int4*)dst);
    scan_fused_kernel<<<NB, CHUNK>>>();
    bin_kernel<<<gE4, TB>>>((const int4*)src, (const int4*)dst);

    // Join: agg1 needs bin (main) + h1/inv_out (side).
    cudaStreamWaitEvent(0, g_e1, 0);
    agg1_kernel<<<gWN, TB>>>(b1);
    agg2_kernel<<<gWN, TB>>>(W2, b2, out);
}